// round 9
// baseline (speedup 1.0000x reference)
#include <cuda_runtime.h>
#include <cuda_bf16.h>
#include <cstdint>

#define NN 50000
#define EE 800000
#define DD 128
#define BUCKET 64
#define GRIDP 148
#define NT64 782             // ceil(50000/64)
#define NT32 1563            // ceil(50000/32)

// ---------------- scratch (static device globals) ----------------
__device__ float g_y0[(size_t)NN * DD];
__device__ __nv_bfloat16 g_Ahi[(size_t)NN * DD];
__device__ __nv_bfloat16 g_Alo[(size_t)NN * DD];
__device__ __nv_bfloat16 g_Hhi[(size_t)NN * 2 * DD];
__device__ __nv_bfloat16 g_Hlo[(size_t)NN * 2 * DD];
__device__ __nv_bfloat16 g_Wt[8][256 * 128];
__device__ int g_cnt[NN];
__device__ uint32_t g_payload[(size_t)NN * BUCKET];

// ---------------- PTX helpers (base ISA only) ----------------
__device__ __forceinline__ uint32_t smem_u32(const void* p) {
    uint32_t a;
    asm("{ .reg .u64 t; cvta.to.shared.u64 t, %1; cvt.u32.u64 %0, t; }" : "=r"(a) : "l"(p));
    return a;
}
__device__ __forceinline__ void cp_async16(uint32_t dst, const void* src, int srcbytes) {
    asm volatile("cp.async.cg.shared.global [%0], [%1], 16, %2;"
                 :: "r"(dst), "l"(src), "r"(srcbytes) : "memory");
}
__device__ __forceinline__ void cp_commit() { asm volatile("cp.async.commit_group;" ::: "memory"); }
__device__ __forceinline__ void cp_wait0()  { asm volatile("cp.async.wait_group 0;" ::: "memory"); }

__device__ __forceinline__ void ldsm_x4(uint32_t& r0, uint32_t& r1, uint32_t& r2, uint32_t& r3,
                                        uint32_t addr) {
    asm volatile("ldmatrix.sync.aligned.m8n8.x4.shared.b16 {%0,%1,%2,%3}, [%4];"
                 : "=r"(r0), "=r"(r1), "=r"(r2), "=r"(r3) : "r"(addr));
}
__device__ __forceinline__ void mma16816(float* d, const uint32_t* a, const uint32_t* b) {
    asm volatile(
        "mma.sync.aligned.m16n8k16.row.col.f32.bf16.bf16.f32 "
        "{%0,%1,%2,%3}, {%4,%5,%6,%7}, {%8,%9}, {%0,%1,%2,%3};"
        : "+f"(d[0]), "+f"(d[1]), "+f"(d[2]), "+f"(d[3])
        : "r"(a[0]), "r"(a[1]), "r"(a[2]), "r"(a[3]), "r"(b[0]), "r"(b[1]));
}

// ---------------- prep: weight transposes + zero cnt ----------------
__global__ void __launch_bounds__(256)
prep_kernel(const float* __restrict__ W10, const float* __restrict__ W20,
            const float* __restrict__ W11, const float* __restrict__ W21,
            __nv_bfloat16* __restrict__ wt, int* __restrict__ cnt) {
    int b = blockIdx.x;
    if (b >= 512) {
        int i = (b - 512) * 256 + threadIdx.x;
        if (i < NN) cnt[i] = 0;
        return;
    }
    int which = b >> 7;
    int i = ((b & 127) << 8) + threadIdx.x;
    const float* W;
    int K, N;
    if (which == 0)      { W = W10; K = 128; N = 256; }
    else if (which == 1) { W = W20; K = 256; N = 128; }
    else if (which == 2) { W = W11; K = 128; N = 256; }
    else                 { W = W21; K = 256; N = 128; }
    int k = i / N, n = i % N;
    float a = W[i];
    __nv_bfloat16 h = __float2bfloat16_rn(a);
    __nv_bfloat16 l = __float2bfloat16_rn(a - __bfloat162float(h));
    __nv_bfloat16* thi = wt + (size_t)(2 * which) * 32768;
    __nv_bfloat16* tlo = thi + 32768;
    thi[n * K + k] = h;
    tlo[n * K + k] = l;
}

// ---------------- bucket fill ----------------
__global__ void __launch_bounds__(256)
fill_kernel(const int* __restrict__ ei, const int* __restrict__ ea,
            int* __restrict__ cnt, uint32_t* __restrict__ payload, int E) {
    int e = blockIdx.x * 256 + threadIdx.x;
    if (e >= E) return;
    int src = ei[e];
    int dst = ei[E + e];
    int a0 = ea[2 * e];
    int a1 = ea[2 * e + 1];
    int pos = atomicAdd(&cnt[dst], 1);
    payload[((size_t)dst << 6) + pos] = (uint32_t)src | ((uint32_t)(a0 * 3 + a1) << 16);
}

// ---------------- gather -> bf16 hi/lo ----------------
__global__ void __launch_bounds__(256)
gather_kernel(const float* __restrict__ x,
              const int* __restrict__ cnt, const uint32_t* __restrict__ payload,
              const float* __restrict__ ee1, const float* __restrict__ ee2,
              __nv_bfloat16* __restrict__ Ahi, __nv_bfloat16* __restrict__ Alo,
              int N) {
    __shared__ float combo[18 * 128];
    const int tid = threadIdx.x;
#pragma unroll
    for (int k = 0; k < 9; k++) {
        int idx = tid + k * 256;
        int c = idx >> 7, d = idx & 127;
        combo[idx] = ee1[(c / 3) * 128 + d] + ee2[(c % 3) * 128 + d];
    }
    __syncthreads();

    const int lane = tid & 31;
    const int n = blockIdx.x * 8 + (tid >> 5);
    if (n >= N) return;
    const int d4 = lane * 4;

    const uint32_t* pl = payload + ((size_t)n << 6);
    int deg = cnt[n];
    float4 acc = make_float4(0.f, 0.f, 0.f, 0.f);
    int i = 0;
    for (; i + 3 < deg; i += 4) {
        uint32_t p0 = pl[i], p1 = pl[i + 1], p2 = pl[i + 2], p3 = pl[i + 3];
        float4 x0 = *(const float4*)(x + (size_t)(p0 & 0xFFFF) * 128 + d4);
        float4 x1 = *(const float4*)(x + (size_t)(p1 & 0xFFFF) * 128 + d4);
        float4 x2 = *(const float4*)(x + (size_t)(p2 & 0xFFFF) * 128 + d4);
        float4 x3 = *(const float4*)(x + (size_t)(p3 & 0xFFFF) * 128 + d4);
        float4 c0 = *(const float4*)(combo + (p0 >> 16) * 128 + d4);
        float4 c1 = *(const float4*)(combo + (p1 >> 16) * 128 + d4);
        float4 c2 = *(const float4*)(combo + (p2 >> 16) * 128 + d4);
        float4 c3 = *(const float4*)(combo + (p3 >> 16) * 128 + d4);
        acc.x += (x0.x + c0.x) + (x1.x + c1.x) + (x2.x + c2.x) + (x3.x + c3.x);
        acc.y += (x0.y + c0.y) + (x1.y + c1.y) + (x2.y + c2.y) + (x3.y + c3.y);
        acc.z += (x0.z + c0.z) + (x1.z + c1.z) + (x2.z + c2.z) + (x3.z + c3.z);
        acc.w += (x0.w + c0.w) + (x1.w + c1.w) + (x2.w + c2.w) + (x3.w + c3.w);
    }
    for (; i < deg; i++) {
        uint32_t p0 = pl[i];
        float4 x0 = *(const float4*)(x + (size_t)(p0 & 0xFFFF) * 128 + d4);
        float4 c0 = *(const float4*)(combo + (p0 >> 16) * 128 + d4);
        acc.x += x0.x + c0.x;
        acc.y += x0.y + c0.y;
        acc.z += x0.z + c0.z;
        acc.w += x0.w + c0.w;
    }

    __nv_bfloat16 h0 = __float2bfloat16_rn(acc.x), h1 = __float2bfloat16_rn(acc.y);
    __nv_bfloat16 h2 = __float2bfloat16_rn(acc.z), h3 = __float2bfloat16_rn(acc.w);
    __nv_bfloat16 l0 = __float2bfloat16_rn(acc.x - __bfloat162float(h0));
    __nv_bfloat16 l1 = __float2bfloat16_rn(acc.y - __bfloat162float(h1));
    __nv_bfloat16 l2 = __float2bfloat16_rn(acc.z - __bfloat162float(h2));
    __nv_bfloat16 l3 = __float2bfloat16_rn(acc.w - __bfloat162float(h3));
    __nv_bfloat162 hp0(h0, h1), hp1(h2, h3), lp0(l0, l1), lp1(l2, l3);
    size_t o = (size_t)n * 128 + d4;
    *(uint2*)(Ahi + o) = make_uint2(*(uint32_t*)&hp0, *(uint32_t*)&hp1);
    *(uint2*)(Alo + o) = make_uint2(*(uint32_t*)&lp0, *(uint32_t*)&lp1);
}

// =============== persistent GEMM 1: H = relu(A @ Wt1^T + b1) ================
// A [M,128] bf16 hi/lo streamed. Wt1 [256,128] hi/lo RESIDENT. M-tile 64,
// 16 warps, warp tile 32x32 (wm=(wid&1)*32, wn=(wid>>1)*32).
#define SROWB 272
#define G1_B (256 * SROWB)            // 69632 per matrix
#define G1_AB (64 * SROWB)            // 17408 per matrix
#define G1_ABUF (2 * G1_AB)           // 34816 per buffer (hi+lo)
#define G1_SMEM (2 * G1_B + 2 * G1_ABUF)   // 208896

__global__ void __launch_bounds__(512, 1)
gemm1p(const __nv_bfloat16* __restrict__ Ahi, const __nv_bfloat16* __restrict__ Alo,
       const __nv_bfloat16* __restrict__ Bhi, const __nv_bfloat16* __restrict__ Blo,
       const float* __restrict__ bias,
       __nv_bfloat16* __restrict__ Hhi, __nv_bfloat16* __restrict__ Hlo, int M) {
    extern __shared__ char smem[];
    const uint32_t sb = smem_u32(smem);
    const uint32_t sBhi = sb;
    const uint32_t sBlo = sb + G1_B;
    const uint32_t sA0  = sb + 2 * G1_B;   // buf: [Ahi | Alo]

    const int tid  = threadIdx.x;
    const int lane = tid & 31;
    const int wid  = tid >> 5;
    const int wm   = (wid & 1) * 32;
    const int wn   = (wid >> 1) * 32;

    // ---- load resident B: 256 rows x 256B, hi+lo ----
#pragma unroll
    for (int i = 0; i < 8; i++) {
        int id = tid + i * 512;
        int row = id >> 4, off = (id & 15) * 16;
        uint32_t sdst = (uint32_t)(row * SROWB + off);
        cp_async16(sBhi + sdst, (const char*)(Bhi + (size_t)row * 128) + off, 16);
        cp_async16(sBlo + sdst, (const char*)(Blo + (size_t)row * 128) + off, 16);
    }

    // ---- issue first A tile: 64 rows x 256B hi+lo ----
    int t = blockIdx.x;
    if (t < NT64) {
#pragma unroll
        for (int i = 0; i < 2; i++) {
            int id = tid + i * 512;
            int row = id >> 4, off = (id & 15) * 16;
            int grow = t * 64 + row;
            int asz = grow < M ? 16 : 0;
            uint32_t sdst = (uint32_t)(row * SROWB + off);
            cp_async16(sA0 + sdst, (const char*)(Ahi + (size_t)grow * 128) + off, asz);
            cp_async16(sA0 + G1_AB + sdst, (const char*)(Alo + (size_t)grow * 128) + off, asz);
        }
    }
    cp_commit();

    int buf = 0;
    for (; t < NT64; t += GRIDP) {
        cp_wait0();
        __syncthreads();

        int tn = t + GRIDP;
        if (tn < NT64) {
            uint32_t base = sA0 + (buf ^ 1) * G1_ABUF;
#pragma unroll
            for (int i = 0; i < 2; i++) {
                int id = tid + i * 512;
                int row = id >> 4, off = (id & 15) * 16;
                int grow = tn * 64 + row;
                int asz = grow < M ? 16 : 0;
                uint32_t sdst = (uint32_t)(row * SROWB + off);
                cp_async16(base + sdst, (const char*)(Ahi + (size_t)grow * 128) + off, asz);
                cp_async16(base + G1_AB + sdst, (const char*)(Alo + (size_t)grow * 128) + off, asz);
            }
        }
        cp_commit();

        const uint32_t cAhi = sA0 + buf * G1_ABUF;
        const uint32_t cAlo = cAhi + G1_AB;
        float acc[2][4][4];
#pragma unroll
        for (int i = 0; i < 2; i++)
#pragma unroll
            for (int j = 0; j < 4; j++)
#pragma unroll
                for (int k = 0; k < 4; k++) acc[i][j][k] = 0.f;

#pragma unroll
        for (int kk = 0; kk < 8; kk++) {
            const uint32_t kb = (uint32_t)(kk * 32);
            uint32_t ah[2][4], al[2][4];
#pragma unroll
            for (int mt = 0; mt < 2; mt++) {
                uint32_t arow = (uint32_t)(wm + mt * 16 + (lane & 15));
                uint32_t aoff = arow * SROWB + kb + ((lane >> 4) << 4);
                ldsm_x4(ah[mt][0], ah[mt][1], ah[mt][2], ah[mt][3], cAhi + aoff);
                ldsm_x4(al[mt][0], al[mt][1], al[mt][2], al[mt][3], cAlo + aoff);
            }
            uint32_t bh[4][2], bl[4][2];
#pragma unroll
            for (int np = 0; np < 2; np++) {
                int g = lane >> 3, r = lane & 7;
                uint32_t browi = (uint32_t)(wn + np * 16 + ((g & 2) ? 8 : 0) + r);
                uint32_t boff = browi * SROWB + kb + ((g & 1) << 4);
                uint32_t r0, r1, r2, r3;
                ldsm_x4(r0, r1, r2, r3, sBhi + boff);
                bh[np * 2][0] = r0; bh[np * 2][1] = r1;
                bh[np * 2 + 1][0] = r2; bh[np * 2 + 1][1] = r3;
                ldsm_x4(r0, r1, r2, r3, sBlo + boff);
                bl[np * 2][0] = r0; bl[np * 2][1] = r1;
                bl[np * 2 + 1][0] = r2; bl[np * 2 + 1][1] = r3;
            }
#pragma unroll
            for (int mt = 0; mt < 2; mt++)
#pragma unroll
                for (int nt = 0; nt < 4; nt++) {
                    mma16816(acc[mt][nt], ah[mt], bh[nt]);
                    mma16816(acc[mt][nt], ah[mt], bl[nt]);
                    mma16816(acc[mt][nt], al[mt], bh[nt]);
                }
        }

        const int brow = t * 64;
#pragma unroll
        for (int mt = 0; mt < 2; mt++) {
#pragma unroll
            for (int nt = 0; nt < 4; nt++) {
                int gcol = wn + nt * 8 + (lane & 3) * 2;
                float b0 = bias[gcol], b1 = bias[gcol + 1];
#pragma unroll
                for (int hrow = 0; hrow < 2; hrow++) {
                    int grow = brow + wm + mt * 16 + (lane >> 2) + hrow * 8;
                    if (grow < M) {
                        float o0 = fmaxf(acc[mt][nt][hrow * 2 + 0] + b0, 0.f);
                        float o1 = fmaxf(acc[mt][nt][hrow * 2 + 1] + b1, 0.f);
                        __nv_bfloat16 h0 = __float2bfloat16_rn(o0);
                        __nv_bfloat16 h1 = __float2bfloat16_rn(o1);
                        __nv_bfloat16 l0 = __float2bfloat16_rn(o0 - __bfloat162float(h0));
                        __nv_bfloat16 l1 = __float2bfloat16_rn(o1 - __bfloat162float(h1));
                        __nv_bfloat162 hp(h0, h1), lp(l0, l1);
                        size_t o = (size_t)grow * 256 + gcol;
                        *(__nv_bfloat162*)(Hhi + o) = hp;
                        *(__nv_bfloat162*)(Hlo + o) = lp;
                    }
                }
            }
        }
        buf ^= 1;
    }
}

// =============== persistent GEMM 2: C = act(H @ Wt2^T + b2) =================
// A=H [M,256] bf16 hi/lo. Wt2 [128,256] hi/lo RESIDENT. Tile 32x128, K=256.
#define SROW2 528
#define G2_B (128 * SROW2)
#define G2_AB (32 * SROW2)
#define G2_ABUF (2 * G2_AB)
#define G2_SMEM (2 * G2_B + 2 * G2_ABUF)   // 202752

template <bool RELU>
__global__ void __launch_bounds__(512, 1)
gemm2p(const __nv_bfloat16* __restrict__ Ahi, const __nv_bfloat16* __restrict__ Alo,
       const __nv_bfloat16* __restrict__ Bhi, const __nv_bfloat16* __restrict__ Blo,
       const float* __restrict__ bias, float* __restrict__ C, int M) {
    extern __shared__ char smem[];
    const uint32_t sb = smem_u32(smem);
    const uint32_t sBhi = sb;
    const uint32_t sBlo = sb + G2_B;
    const uint32_t sA0  = sb + 2 * G2_B;

    const int tid  = threadIdx.x;
    const int lane = tid & 31;
    const int wid  = tid >> 5;
    const int wm   = (wid & 1) * 16;
    const int wn   = (wid >> 1) * 16;

#pragma unroll
    for (int i = 0; i < 8; i++) {
        int id = tid + i * 512;
        int row = id >> 5, off = (id & 31) * 16;
        uint32_t sdst = (uint32_t)(row * SROW2 + off);
        cp_async16(sBhi + sdst, (const char*)(Bhi + (size_t)row * 256) + off, 16);
        cp_async16(sBlo + sdst, (const char*)(Blo + (size_t)row * 256) + off, 16);
    }

    int t = blockIdx.x;
    if (t < NT32) {
#pragma unroll
        for (int i = 0; i < 2; i++) {
            int id = tid + i * 512;
            int row = id >> 5, off = (id & 31) * 16;
            int grow = t * 32 + row;
            int asz = grow < M ? 16 : 0;
            uint32_t sdst = (uint32_t)(row * SROW2 + off);
            cp_async16(sA0 + sdst, (const char*)(Ahi + (size_t)grow * 256) + off, asz);
            cp_async16(sA0 + G2_AB + sdst, (const char*)(Alo + (size_t)grow * 256) + off, asz);
        }
    }
    cp_commit();

    int buf = 0;
    for (; t < NT32; t += GRIDP) {
        cp_wait0();
        __syncthreads();

        int tn = t + GRIDP;
        if (tn < NT32) {
            uint32_t base = sA0 + (buf ^ 1) * G2_ABUF;
#pragma unroll
            for (int i = 0; i < 2; i++) {
                int id = tid + i * 512;
                int row = id >> 5, off = (id & 31) * 16;
                int grow = tn * 32 + row;
                int asz = grow < M ? 16 : 0;
                uint32_t sdst = (uint32_t)(row * SROW2 + off);
                cp_async16(base + sdst, (const char*)(Ahi + (size_t)grow * 256) + off, asz);
                cp_async16(base + G2_AB + sdst, (const char*)(Alo + (size_t)grow * 256) + off, asz);
            }
        }
        cp_commit();

        const uint32_t cAhi = sA0 + buf * G2_ABUF;
        const uint32_t cAlo = cAhi + G2_AB;
        float acc[2][4];
#pragma unroll
        for (int j = 0; j < 2; j++)
#pragma unroll
            for (int k = 0; k < 4; k++) acc[j][k] = 0.f;

#pragma unroll
        for (int kk = 0; kk < 16; kk++) {
            const uint32_t kb = (uint32_t)(kk * 32);
            uint32_t ah[4], al[4];
            {
                uint32_t arow = (uint32_t)(wm + (lane & 15));
                uint32_t aoff = arow * SROW2 + kb + ((lane >> 4) << 4);
                ldsm_x4(ah[0], ah[1], ah[2], ah[3], cAhi + aoff);
                ldsm_x4(al[0], al[1], al[2], al[3], cAlo + aoff);
            }
            uint32_t bh[2][2], bl[2][2];
            {
                int g = lane >> 3, r = lane & 7;
                uint32_t browi = (uint32_t)(wn + ((g & 2) ? 8 : 0) + r);
                uint32_t boff = browi * SROW2 + kb + ((g & 1) << 4);
                uint32_t r0, r1, r2, r3;
                ldsm_x4(r0, r1, r2, r3, sBhi + boff);
                bh[0][0] = r0; bh[0][1] = r1;
                bh[1][0] = r2; bh[1][1] = r3;
                ldsm_x4(r0, r1, r2, r3, sBlo + boff);
                bl[0][0] = r0; bl[0][1] = r1;
                bl[1][0] = r2; bl[1][1] = r3;
            }
#pragma unroll
            for (int nt = 0; nt < 2; nt++) {
                mma16816(acc[nt], ah, bh[nt]);
                mma16816(acc[nt], ah, bl[nt]);
                mma16816(acc[nt], al, bh[nt]);
            }
        }

        const int brow = t * 32;
#pragma unroll
        for (int nt = 0; nt < 2; nt++) {
            int gcol = wn + nt * 8 + (lane & 3) * 2;
            float b0 = bias[gcol], b1 = bias[gcol + 1];
#pragma unroll
            for (int hrow = 0; hrow < 2; hrow++) {
                int grow = brow + wm + (lane >> 2) + hrow * 8;
                if (grow < M) {
                    float o0 = acc[nt][hrow * 2 + 0] + b0;
                    float o1 = acc[nt][hrow * 2 + 1] + b1;
                    if (RELU) { o0 = fmaxf(o0, 0.f); o1 = fmaxf(o1, 0.f); }
                    *(float2*)(C + (size_t)grow * 128 + gcol) = make_float2(o0, o1);
                }
            }
        }
        buf ^= 1;
    }
}

// ---------------- launch ----------------
extern "C" void kernel_launch(void* const* d_in, const int* in_sizes, int n_in,
                              void* d_out, int out_size) {
    const float* x     = (const float*)d_in[0];
    const int*   ei    = (const int*)d_in[1];
    const int*   ea    = (const int*)d_in[2];
    const float* ee1_0 = (const float*)d_in[3];
    const float* ee2_0 = (const float*)d_in[4];
    const float* W1_0  = (const float*)d_in[5];
    const float* b1_0  = (const float*)d_in[6];
    const float* W2_0  = (const float*)d_in[7];
    const float* b2_0  = (const float*)d_in[8];
    const float* ee1_1 = (const float*)d_in[9];
    const float* ee2_1 = (const float*)d_in[10];
    const float* W1_1  = (const float*)d_in[11];
    const float* b1_1  = (const float*)d_in[12];
    const float* W2_1  = (const float*)d_in[13];
    const float* b2_1  = (const float*)d_in[14];
    float* out = (float*)d_out;

    const int N = in_sizes[0] / DD;
    const int E = in_sizes[1] / 2;

    float *y0;
    __nv_bfloat16 *Ahi, *Alo, *Hhi, *Hlo, *Wt;
    int* cnt;
    uint32_t* payload;
    cudaGetSymbolAddress((void**)&y0, g_y0);
    cudaGetSymbolAddress((void**)&Ahi, g_Ahi);
    cudaGetSymbolAddress((void**)&Alo, g_Alo);
    cudaGetSymbolAddress((void**)&Hhi, g_Hhi);
    cudaGetSymbolAddress((void**)&Hlo, g_Hlo);
    cudaGetSymbolAddress((void**)&Wt, g_Wt);
    cudaGetSymbolAddress((void**)&cnt, g_cnt);
    cudaGetSymbolAddress((void**)&payload, g_payload);

    cudaFuncSetAttribute(gemm1p, cudaFuncAttributeMaxDynamicSharedMemorySize, G1_SMEM);
    cudaFuncSetAttribute(gemm2p<true>, cudaFuncAttributeMaxDynamicSharedMemorySize, G2_SMEM);
    cudaFuncSetAttribute(gemm2p<false>, cudaFuncAttributeMaxDynamicSharedMemorySize, G2_SMEM);

    const int ggrid = (N + 7) / 8;

    prep_kernel<<<512 + (NN + 255) / 256, 256>>>(W1_0, W2_0, W1_1, W2_1, Wt, cnt);
    fill_kernel<<<(E + 255) / 256, 256>>>(ei, ea, cnt, payload, E);

    // ============ layer 0 ============
    gather_kernel<<<ggrid, 256>>>(x, cnt, payload, ee1_0, ee2_0, Ahi, Alo, N);
    gemm1p<<<GRIDP, 512, G1_SMEM>>>(Ahi, Alo, Wt + 0 * 32768, Wt + 1 * 32768, b1_0, Hhi, Hlo, N);
    gemm2p<true><<<GRIDP, 512, G2_SMEM>>>(Hhi, Hlo, Wt + 2 * 32768, Wt + 3 * 32768, b2_0, y0, N);

    // ============ layer 1 ============
    gather_kernel<<<ggrid, 256>>>(y0, cnt, payload, ee1_1, ee2_1, Ahi, Alo, N);
    gemm1p<<<GRIDP, 512, G1_SMEM>>>(Ahi, Alo, Wt + 4 * 32768, Wt + 5 * 32768, b1_1, Hhi, Hlo, N);
    gemm2p<false><<<GRIDP, 512, G2_SMEM>>>(Hhi, Hlo, Wt + 6 * 32768, Wt + 7 * 32768, b2_1, out, N);
}

// round 10
// speedup vs baseline: 1.0073x; 1.0073x over previous
#include <cuda_runtime.h>
#include <cuda_bf16.h>
#include <cstdint>

#define NN 50000
#define EE 800000
#define DD 128
#define BUCKET 64
#define GRIDP 148
#define NT64 782             // ceil(50000/64)
#define NT32 1563            // ceil(50000/32)

// ---------------- scratch (static device globals) ----------------
__device__ float g_y0[(size_t)NN * DD];
__device__ __nv_bfloat16 g_Ahi[(size_t)NN * DD];
__device__ __nv_bfloat16 g_Alo[(size_t)NN * DD];
__device__ __nv_bfloat16 g_Hhi[(size_t)NN * 2 * DD];
__device__ __nv_bfloat16 g_Hlo[(size_t)NN * 2 * DD];
__device__ __nv_bfloat16 g_Wt[8][256 * 128];
__device__ int g_cnt[NN];
__device__ uint32_t g_payload[(size_t)NN * BUCKET];

// ---------------- PTX helpers (base ISA only) ----------------
__device__ __forceinline__ uint32_t smem_u32(const void* p) {
    uint32_t a;
    asm("{ .reg .u64 t; cvta.to.shared.u64 t, %1; cvt.u32.u64 %0, t; }" : "=r"(a) : "l"(p));
    return a;
}
__device__ __forceinline__ void cp_async16(uint32_t dst, const void* src, int srcbytes) {
    asm volatile("cp.async.cg.shared.global [%0], [%1], 16, %2;"
                 :: "r"(dst), "l"(src), "r"(srcbytes) : "memory");
}
__device__ __forceinline__ void cp_commit() { asm volatile("cp.async.commit_group;" ::: "memory"); }
__device__ __forceinline__ void cp_wait0()  { asm volatile("cp.async.wait_group 0;" ::: "memory"); }

__device__ __forceinline__ void ldsm_x4(uint32_t& r0, uint32_t& r1, uint32_t& r2, uint32_t& r3,
                                        uint32_t addr) {
    asm volatile("ldmatrix.sync.aligned.m8n8.x4.shared.b16 {%0,%1,%2,%3}, [%4];"
                 : "=r"(r0), "=r"(r1), "=r"(r2), "=r"(r3) : "r"(addr));
}
__device__ __forceinline__ void mma16816(float* d, const uint32_t* a, const uint32_t* b) {
    asm volatile(
        "mma.sync.aligned.m16n8k16.row.col.f32.bf16.bf16.f32 "
        "{%0,%1,%2,%3}, {%4,%5,%6,%7}, {%8,%9}, {%0,%1,%2,%3};"
        : "+f"(d[0]), "+f"(d[1]), "+f"(d[2]), "+f"(d[3])
        : "r"(a[0]), "r"(a[1]), "r"(a[2]), "r"(a[3]), "r"(b[0]), "r"(b[1]));
}

// ---------------- prep: weight transposes + zero cnt ----------------
__global__ void __launch_bounds__(256)
prep_kernel(const float* __restrict__ W10, const float* __restrict__ W20,
            const float* __restrict__ W11, const float* __restrict__ W21,
            __nv_bfloat16* __restrict__ wt, int* __restrict__ cnt) {
    int b = blockIdx.x;
    if (b >= 512) {
        int i = (b - 512) * 256 + threadIdx.x;
        if (i < NN) cnt[i] = 0;
        return;
    }
    int which = b >> 7;
    int i = ((b & 127) << 8) + threadIdx.x;
    const float* W;
    int K, N;
    if (which == 0)      { W = W10; K = 128; N = 256; }
    else if (which == 1) { W = W20; K = 256; N = 128; }
    else if (which == 2) { W = W11; K = 128; N = 256; }
    else                 { W = W21; K = 256; N = 128; }
    int k = i / N, n = i % N;
    float a = W[i];
    __nv_bfloat16 h = __float2bfloat16_rn(a);
    __nv_bfloat16 l = __float2bfloat16_rn(a - __bfloat162float(h));
    __nv_bfloat16* thi = wt + (size_t)(2 * which) * 32768;
    __nv_bfloat16* tlo = thi + 32768;
    thi[n * K + k] = h;
    tlo[n * K + k] = l;
}

// ---------------- bucket fill ----------------
__global__ void __launch_bounds__(256)
fill_kernel(const int* __restrict__ ei, const int* __restrict__ ea,
            int* __restrict__ cnt, uint32_t* __restrict__ payload, int E) {
    int e = blockIdx.x * 256 + threadIdx.x;
    if (e >= E) return;
    int src = ei[e];
    int dst = ei[E + e];
    int a0 = ea[2 * e];
    int a1 = ea[2 * e + 1];
    int pos = atomicAdd(&cnt[dst], 1);
    payload[((size_t)dst << 6) + pos] = (uint32_t)src | ((uint32_t)(a0 * 3 + a1) << 16);
}

// ---------------- gather -> bf16 hi/lo ----------------
__global__ void __launch_bounds__(256)
gather_kernel(const float* __restrict__ x,
              const int* __restrict__ cnt, const uint32_t* __restrict__ payload,
              const float* __restrict__ ee1, const float* __restrict__ ee2,
              __nv_bfloat16* __restrict__ Ahi, __nv_bfloat16* __restrict__ Alo,
              int N) {
    __shared__ float combo[18 * 128];
    const int tid = threadIdx.x;
#pragma unroll
    for (int k = 0; k < 9; k++) {
        int idx = tid + k * 256;
        int c = idx >> 7, d = idx & 127;
        combo[idx] = ee1[(c / 3) * 128 + d] + ee2[(c % 3) * 128 + d];
    }
    __syncthreads();

    const int lane = tid & 31;
    const int n = blockIdx.x * 8 + (tid >> 5);
    if (n >= N) return;
    const int d4 = lane * 4;

    const uint32_t* pl = payload + ((size_t)n << 6);
    int deg = cnt[n];
    float4 acc = make_float4(0.f, 0.f, 0.f, 0.f);
    int i = 0;
    for (; i + 3 < deg; i += 4) {
        uint32_t p0 = pl[i], p1 = pl[i + 1], p2 = pl[i + 2], p3 = pl[i + 3];
        float4 x0 = *(const float4*)(x + (size_t)(p0 & 0xFFFF) * 128 + d4);
        float4 x1 = *(const float4*)(x + (size_t)(p1 & 0xFFFF) * 128 + d4);
        float4 x2 = *(const float4*)(x + (size_t)(p2 & 0xFFFF) * 128 + d4);
        float4 x3 = *(const float4*)(x + (size_t)(p3 & 0xFFFF) * 128 + d4);
        float4 c0 = *(const float4*)(combo + (p0 >> 16) * 128 + d4);
        float4 c1 = *(const float4*)(combo + (p1 >> 16) * 128 + d4);
        float4 c2 = *(const float4*)(combo + (p2 >> 16) * 128 + d4);
        float4 c3 = *(const float4*)(combo + (p3 >> 16) * 128 + d4);
        acc.x += (x0.x + c0.x) + (x1.x + c1.x) + (x2.x + c2.x) + (x3.x + c3.x);
        acc.y += (x0.y + c0.y) + (x1.y + c1.y) + (x2.y + c2.y) + (x3.y + c3.y);
        acc.z += (x0.z + c0.z) + (x1.z + c1.z) + (x2.z + c2.z) + (x3.z + c3.z);
        acc.w += (x0.w + c0.w) + (x1.w + c1.w) + (x2.w + c2.w) + (x3.w + c3.w);
    }
    for (; i < deg; i++) {
        uint32_t p0 = pl[i];
        float4 x0 = *(const float4*)(x + (size_t)(p0 & 0xFFFF) * 128 + d4);
        float4 c0 = *(const float4*)(combo + (p0 >> 16) * 128 + d4);
        acc.x += x0.x + c0.x;
        acc.y += x0.y + c0.y;
        acc.z += x0.z + c0.z;
        acc.w += x0.w + c0.w;
    }

    __nv_bfloat16 h0 = __float2bfloat16_rn(acc.x), h1 = __float2bfloat16_rn(acc.y);
    __nv_bfloat16 h2 = __float2bfloat16_rn(acc.z), h3 = __float2bfloat16_rn(acc.w);
    __nv_bfloat16 l0 = __float2bfloat16_rn(acc.x - __bfloat162float(h0));
    __nv_bfloat16 l1 = __float2bfloat16_rn(acc.y - __bfloat162float(h1));
    __nv_bfloat16 l2 = __float2bfloat16_rn(acc.z - __bfloat162float(h2));
    __nv_bfloat16 l3 = __float2bfloat16_rn(acc.w - __bfloat162float(h3));
    __nv_bfloat162 hp0(h0, h1), hp1(h2, h3), lp0(l0, l1), lp1(l2, l3);
    size_t o = (size_t)n * 128 + d4;
    *(uint2*)(Ahi + o) = make_uint2(*(uint32_t*)&hp0, *(uint32_t*)&hp1);
    *(uint2*)(Alo + o) = make_uint2(*(uint32_t*)&lp0, *(uint32_t*)&lp1);
}

// =============== persistent GEMM 1: H = relu(A @ Wt1^T + b1) ================
// 256 threads = 8 warps, warp tile 32x64 (wm=(wid&1)*32, wn=(wid>>1)*64).
// A [M,128] streamed (M-tile 64, double-buffered). Wt1 [256,128] RESIDENT.
#define SROWB 272
#define G1_B (256 * SROWB)            // 69632 per matrix
#define G1_AB (64 * SROWB)            // 17408 per matrix
#define G1_ABUF (2 * G1_AB)           // 34816 per buffer (hi+lo)
#define G1_SMEM (2 * G1_B + 2 * G1_ABUF)   // 208896

__global__ void __launch_bounds__(256, 1)
gemm1p(const __nv_bfloat16* __restrict__ Ahi, const __nv_bfloat16* __restrict__ Alo,
       const __nv_bfloat16* __restrict__ Bhi, const __nv_bfloat16* __restrict__ Blo,
       const float* __restrict__ bias,
       __nv_bfloat16* __restrict__ Hhi, __nv_bfloat16* __restrict__ Hlo, int M) {
    extern __shared__ char smem[];
    const uint32_t sb = smem_u32(smem);
    const uint32_t sBhi = sb;
    const uint32_t sBlo = sb + G1_B;
    const uint32_t sA0  = sb + 2 * G1_B;   // buf: [Ahi | Alo]

    const int tid  = threadIdx.x;
    const int lane = tid & 31;
    const int wid  = tid >> 5;
    const int wm   = (wid & 1) * 32;
    const int wn   = (wid >> 1) * 64;

    // ---- load resident B: 256 rows x 256B, hi+lo ----
#pragma unroll
    for (int i = 0; i < 16; i++) {
        int id = tid + i * 256;
        int row = id >> 4, off = (id & 15) * 16;
        uint32_t sdst = (uint32_t)(row * SROWB + off);
        cp_async16(sBhi + sdst, (const char*)(Bhi + (size_t)row * 128) + off, 16);
        cp_async16(sBlo + sdst, (const char*)(Blo + (size_t)row * 128) + off, 16);
    }

    // ---- issue first A tile: 64 rows x 256B hi+lo ----
    int t = blockIdx.x;
    if (t < NT64) {
#pragma unroll
        for (int i = 0; i < 4; i++) {
            int id = tid + i * 256;
            int row = id >> 4, off = (id & 15) * 16;
            int grow = t * 64 + row;
            int asz = grow < M ? 16 : 0;
            uint32_t sdst = (uint32_t)(row * SROWB + off);
            cp_async16(sA0 + sdst, (const char*)(Ahi + (size_t)grow * 128) + off, asz);
            cp_async16(sA0 + G1_AB + sdst, (const char*)(Alo + (size_t)grow * 128) + off, asz);
        }
    }
    cp_commit();

    int buf = 0;
    for (; t < NT64; t += GRIDP) {
        cp_wait0();
        __syncthreads();

        int tn = t + GRIDP;
        if (tn < NT64) {
            uint32_t base = sA0 + (buf ^ 1) * G1_ABUF;
#pragma unroll
            for (int i = 0; i < 4; i++) {
                int id = tid + i * 256;
                int row = id >> 4, off = (id & 15) * 16;
                int grow = tn * 64 + row;
                int asz = grow < M ? 16 : 0;
                uint32_t sdst = (uint32_t)(row * SROWB + off);
                cp_async16(base + sdst, (const char*)(Ahi + (size_t)grow * 128) + off, asz);
                cp_async16(base + G1_AB + sdst, (const char*)(Alo + (size_t)grow * 128) + off, asz);
            }
        }
        cp_commit();

        const uint32_t cAhi = sA0 + buf * G1_ABUF;
        const uint32_t cAlo = cAhi + G1_AB;
        float acc[2][8][4];
#pragma unroll
        for (int i = 0; i < 2; i++)
#pragma unroll
            for (int j = 0; j < 8; j++)
#pragma unroll
                for (int k = 0; k < 4; k++) acc[i][j][k] = 0.f;

#pragma unroll
        for (int kk = 0; kk < 8; kk++) {
            const uint32_t kb = (uint32_t)(kk * 32);
            uint32_t ah[2][4], al[2][4];
#pragma unroll
            for (int mt = 0; mt < 2; mt++) {
                uint32_t arow = (uint32_t)(wm + mt * 16 + (lane & 15));
                uint32_t aoff = arow * SROWB + kb + ((lane >> 4) << 4);
                ldsm_x4(ah[mt][0], ah[mt][1], ah[mt][2], ah[mt][3], cAhi + aoff);
                ldsm_x4(al[mt][0], al[mt][1], al[mt][2], al[mt][3], cAlo + aoff);
            }
            uint32_t bh[8][2], bl[8][2];
#pragma unroll
            for (int np = 0; np < 4; np++) {
                int g = lane >> 3, r = lane & 7;
                uint32_t browi = (uint32_t)(wn + np * 16 + ((g & 2) ? 8 : 0) + r);
                uint32_t boff = browi * SROWB + kb + ((g & 1) << 4);
                uint32_t r0, r1, r2, r3;
                ldsm_x4(r0, r1, r2, r3, sBhi + boff);
                bh[np * 2][0] = r0; bh[np * 2][1] = r1;
                bh[np * 2 + 1][0] = r2; bh[np * 2 + 1][1] = r3;
                ldsm_x4(r0, r1, r2, r3, sBlo + boff);
                bl[np * 2][0] = r0; bl[np * 2][1] = r1;
                bl[np * 2 + 1][0] = r2; bl[np * 2 + 1][1] = r3;
            }
#pragma unroll
            for (int mt = 0; mt < 2; mt++)
#pragma unroll
                for (int nt = 0; nt < 8; nt++) {
                    mma16816(acc[mt][nt], ah[mt], bh[nt]);
                    mma16816(acc[mt][nt], ah[mt], bl[nt]);
                    mma16816(acc[mt][nt], al[mt], bh[nt]);
                }
        }

        const int brow = t * 64;
#pragma unroll
        for (int mt = 0; mt < 2; mt++) {
#pragma unroll
            for (int nt = 0; nt < 8; nt++) {
                int gcol = wn + nt * 8 + (lane & 3) * 2;
                float b0 = bias[gcol], b1 = bias[gcol + 1];
#pragma unroll
                for (int hrow = 0; hrow < 2; hrow++) {
                    int grow = brow + wm + mt * 16 + (lane >> 2) + hrow * 8;
                    if (grow < M) {
                        float o0 = fmaxf(acc[mt][nt][hrow * 2 + 0] + b0, 0.f);
                        float o1 = fmaxf(acc[mt][nt][hrow * 2 + 1] + b1, 0.f);
                        __nv_bfloat16 h0 = __float2bfloat16_rn(o0);
                        __nv_bfloat16 h1 = __float2bfloat16_rn(o1);
                        __nv_bfloat16 l0 = __float2bfloat16_rn(o0 - __bfloat162float(h0));
                        __nv_bfloat16 l1 = __float2bfloat16_rn(o1 - __bfloat162float(h1));
                        __nv_bfloat162 hp(h0, h1), lp(l0, l1);
                        size_t o = (size_t)grow * 256 + gcol;
                        *(__nv_bfloat162*)(Hhi + o) = hp;
                        *(__nv_bfloat162*)(Hlo + o) = lp;
                    }
                }
            }
        }
        buf ^= 1;
    }
}

// =============== persistent GEMM 2: C = act(H @ Wt2^T + b2) =================
// 256 threads = 8 warps, warp tile 16x32 (wm=(wid&1)*16, wn=(wid>>1)*32).
// A=H [M,256] streamed (M-tile 32, double-buffered). Wt2 [128,256] RESIDENT.
#define SROW2 528
#define G2_B (128 * SROW2)
#define G2_AB (32 * SROW2)
#define G2_ABUF (2 * G2_AB)
#define G2_SMEM (2 * G2_B + 2 * G2_ABUF)   // 202752

template <bool RELU>
__global__ void __launch_bounds__(256, 1)
gemm2p(const __nv_bfloat16* __restrict__ Ahi, const __nv_bfloat16* __restrict__ Alo,
       const __nv_bfloat16* __restrict__ Bhi, const __nv_bfloat16* __restrict__ Blo,
       const float* __restrict__ bias, float* __restrict__ C, int M) {
    extern __shared__ char smem[];
    const uint32_t sb = smem_u32(smem);
    const uint32_t sBhi = sb;
    const uint32_t sBlo = sb + G2_B;
    const uint32_t sA0  = sb + 2 * G2_B;

    const int tid  = threadIdx.x;
    const int lane = tid & 31;
    const int wid  = tid >> 5;
    const int wm   = (wid & 1) * 16;
    const int wn   = (wid >> 1) * 32;

    // ---- load resident B: 128 rows x 512B, hi+lo ----
#pragma unroll
    for (int i = 0; i < 16; i++) {
        int id = tid + i * 256;
        int row = id >> 5, off = (id & 31) * 16;
        uint32_t sdst = (uint32_t)(row * SROW2 + off);
        cp_async16(sBhi + sdst, (const char*)(Bhi + (size_t)row * 256) + off, 16);
        cp_async16(sBlo + sdst, (const char*)(Blo + (size_t)row * 256) + off, 16);
    }

    int t = blockIdx.x;
    if (t < NT32) {
#pragma unroll
        for (int i = 0; i < 4; i++) {
            int id = tid + i * 256;
            int row = id >> 5, off = (id & 31) * 16;
            int grow = t * 32 + row;
            int asz = grow < M ? 16 : 0;
            uint32_t sdst = (uint32_t)(row * SROW2 + off);
            cp_async16(sA0 + sdst, (const char*)(Ahi + (size_t)grow * 256) + off, asz);
            cp_async16(sA0 + G2_AB + sdst, (const char*)(Alo + (size_t)grow * 256) + off, asz);
        }
    }
    cp_commit();

    int buf = 0;
    for (; t < NT32; t += GRIDP) {
        cp_wait0();
        __syncthreads();

        int tn = t + GRIDP;
        if (tn < NT32) {
            uint32_t base = sA0 + (buf ^ 1) * G2_ABUF;
#pragma unroll
            for (int i = 0; i < 4; i++) {
                int id = tid + i * 256;
                int row = id >> 5, off = (id & 31) * 16;
                int grow = tn * 32 + row;
                int asz = grow < M ? 16 : 0;
                uint32_t sdst = (uint32_t)(row * SROW2 + off);
                cp_async16(base + sdst, (const char*)(Ahi + (size_t)grow * 256) + off, asz);
                cp_async16(base + G2_AB + sdst, (const char*)(Alo + (size_t)grow * 256) + off, asz);
            }
        }
        cp_commit();

        const uint32_t cAhi = sA0 + buf * G2_ABUF;
        const uint32_t cAlo = cAhi + G2_AB;
        float acc[4][4];
#pragma unroll
        for (int j = 0; j < 4; j++)
#pragma unroll
            for (int k = 0; k < 4; k++) acc[j][k] = 0.f;

#pragma unroll
        for (int kk = 0; kk < 16; kk++) {
            const uint32_t kb = (uint32_t)(kk * 32);
            uint32_t ah[4], al[4];
            {
                uint32_t arow = (uint32_t)(wm + (lane & 15));
                uint32_t aoff = arow * SROW2 + kb + ((lane >> 4) << 4);
                ldsm_x4(ah[0], ah[1], ah[2], ah[3], cAhi + aoff);
                ldsm_x4(al[0], al[1], al[2], al[3], cAlo + aoff);
            }
            uint32_t bh[4][2], bl[4][2];
#pragma unroll
            for (int np = 0; np < 2; np++) {
                int g = lane >> 3, r = lane & 7;
                uint32_t browi = (uint32_t)(wn + np * 16 + ((g & 2) ? 8 : 0) + r);
                uint32_t boff = browi * SROW2 + kb + ((g & 1) << 4);
                uint32_t r0, r1, r2, r3;
                ldsm_x4(r0, r1, r2, r3, sBhi + boff);
                bh[np * 2][0] = r0; bh[np * 2][1] = r1;
                bh[np * 2 + 1][0] = r2; bh[np * 2 + 1][1] = r3;
                ldsm_x4(r0, r1, r2, r3, sBlo + boff);
                bl[np * 2][0] = r0; bl[np * 2][1] = r1;
                bl[np * 2 + 1][0] = r2; bl[np * 2 + 1][1] = r3;
            }
#pragma unroll
            for (int nt = 0; nt < 4; nt++) {
                mma16816(acc[nt], ah, bh[nt]);
                mma16816(acc[nt], ah, bl[nt]);
                mma16816(acc[nt], al, bh[nt]);
            }
        }

        const int brow = t * 32;
#pragma unroll
        for (int nt = 0; nt < 4; nt++) {
            int gcol = wn + nt * 8 + (lane & 3) * 2;
            float b0 = bias[gcol], b1 = bias[gcol + 1];
#pragma unroll
            for (int hrow = 0; hrow < 2; hrow++) {
                int grow = brow + wm + (lane >> 2) + hrow * 8;
                if (grow < M) {
                    float o0 = acc[nt][hrow * 2 + 0] + b0;
                    float o1 = acc[nt][hrow * 2 + 1] + b1;
                    if (RELU) { o0 = fmaxf(o0, 0.f); o1 = fmaxf(o1, 0.f); }
                    *(float2*)(C + (size_t)grow * 128 + gcol) = make_float2(o0, o1);
                }
            }
        }
        buf ^= 1;
    }
}

// ---------------- launch ----------------
extern "C" void kernel_launch(void* const* d_in, const int* in_sizes, int n_in,
                              void* d_out, int out_size) {
    const float* x     = (const float*)d_in[0];
    const int*   ei    = (const int*)d_in[1];
    const int*   ea    = (const int*)d_in[2];
    const float* ee1_0 = (const float*)d_in[3];
    const float* ee2_0 = (const float*)d_in[4];
    const float* W1_0  = (const float*)d_in[5];
    const float* b1_0  = (const float*)d_in[6];
    const float* W2_0  = (const float*)d_in[7];
    const float* b2_0  = (const float*)d_in[8];
    const float* ee1_1 = (const float*)d_in[9];
    const float* ee2_1 = (const float*)d_in[10];
    const float* W1_1  = (const float*)d_in[11];
    const float* b1_1  = (const float*)d_in[12];
    const float* W2_1  = (const float*)d_in[13];
    const float* b2_1  = (const float*)d_in[14];
    float* out = (float*)d_out;

    const int N = in_sizes[0] / DD;
    const int E = in_sizes[1] / 2;

    float *y0;
    __nv_bfloat16 *Ahi, *Alo, *Hhi, *Hlo, *Wt;
    int* cnt;
    uint32_t* payload;
    cudaGetSymbolAddress((void**)&y0, g_y0);
    cudaGetSymbolAddress((void**)&Ahi, g_Ahi);
    cudaGetSymbolAddress((void**)&Alo, g_Alo);
    cudaGetSymbolAddress((void**)&Hhi, g_Hhi);
    cudaGetSymbolAddress((void**)&Hlo, g_Hlo);
    cudaGetSymbolAddress((void**)&Wt, g_Wt);
    cudaGetSymbolAddress((void**)&cnt, g_cnt);
    cudaGetSymbolAddress((void**)&payload, g_payload);

    cudaFuncSetAttribute(gemm1p, cudaFuncAttributeMaxDynamicSharedMemorySize, G1_SMEM);
    cudaFuncSetAttribute(gemm2p<true>, cudaFuncAttributeMaxDynamicSharedMemorySize, G2_SMEM);
    cudaFuncSetAttribute(gemm2p<false>, cudaFuncAttributeMaxDynamicSharedMemorySize, G2_SMEM);

    const int ggrid = (N + 7) / 8;

    prep_kernel<<<512 + (NN + 255) / 256, 256>>>(W1_0, W2_0, W1_1, W2_1, Wt, cnt);
    fill_kernel<<<(E + 255) / 256, 256>>>(ei, ea, cnt, payload, E);

    // ============ layer 0 ============
    gather_kernel<<<ggrid, 256>>>(x, cnt, payload, ee1_0, ee2_0, Ahi, Alo, N);
    gemm1p<<<GRIDP, 256, G1_SMEM>>>(Ahi, Alo, Wt + 0 * 32768, Wt + 1 * 32768, b1_0, Hhi, Hlo, N);
    gemm2p<true><<<GRIDP, 256, G2_SMEM>>>(Hhi, Hlo, Wt + 2 * 32768, Wt + 3 * 32768, b2_0, y0, N);

    // ============ layer 1 ============
    gather_kernel<<<ggrid, 256>>>(y0, cnt, payload, ee1_1, ee2_1, Ahi, Alo, N);
    gemm1p<<<GRIDP, 256, G1_SMEM>>>(Ahi, Alo, Wt + 4 * 32768, Wt + 5 * 32768, b1_1, Hhi, Hlo, N);
    gemm2p<false><<<GRIDP, 256, G2_SMEM>>>(Hhi, Hlo, Wt + 6 * 32768, Wt + 7 * 32768, b2_1, out, N);
}